// round 6
// baseline (speedup 1.0000x reference)
#include <cuda_runtime.h>

// Problem constants (fixed by the dataset)
#define NMAX   50000
#define EMAX   800000
#define F      64          // feature width of every layer
#define OUTC   192         // concat(x1,x2,x3) width
#define GMAX_BLOCKS 200
#define SCAN_T 1024

// ---------------- scratch (device globals: no allocation allowed) ----------
__device__ int   g_is64;                 // 1 if edge_index is int64, 0 if int32
__device__ int   g_deg[NMAX];
__device__ int   g_rowptr[NMAX + 1];
__device__ int   g_pos[NMAX];
__device__ float g_dinv[NMAX];
__device__ int   g_csr_src[EMAX];
__device__ float g_csr_wt[EMAX];
__device__ __align__(16) float g_h[NMAX * F];   // h = X @ W of current layer
__device__ float g_partial[GMAX_BLOCKS * OUTC];

// ---------------- edge-index dtype detection --------------------------------
// Genuine int64 node ids are < NMAX. int32 data reinterpreted as int64 yields
// huge values (high word = a second node id, nonzero w.p. ~1 across 64 probes).
__global__ void k_detect(const void* __restrict__ ei) {
    if (threadIdx.x == 0) {
        const long long* p = (const long long*)ei;
        int is64 = 1;
        for (int i = 0; i < 64; i++) {
            long long v = p[i];
            if (v < 0 || v >= NMAX) { is64 = 0; break; }
        }
        g_is64 = is64;
    }
}

__device__ __forceinline__ int edge_at(const void* ei, int idx) {
    if (g_is64) return (int)((const long long*)ei)[idx];
    return ((const int*)ei)[idx];
}

// ---------------- degree histogram ------------------------------------------
__global__ void k_deg_zero(int n) {
    int i = blockIdx.x * blockDim.x + threadIdx.x;
    if (i < n) g_deg[i] = 0;
}

__global__ void k_deg_count(const void* __restrict__ ei, int e) {
    int i = blockIdx.x * blockDim.x + threadIdx.x;
    if (i < e) atomicAdd(&g_deg[edge_at(ei, e + i)], 1);   // row 1 = dst
}

// ---------------- single-block exclusive scan over degrees ------------------
__global__ void k_scan(int n) {
    __shared__ int ssum[SCAN_T];
    int tid   = threadIdx.x;
    int chunk = (n + SCAN_T - 1) / SCAN_T;
    int start = tid * chunk;
    int end   = min(n, start + chunk);

    int s = 0;
    for (int i = start; i < end; i++) s += g_deg[i];
    ssum[tid] = s;
    __syncthreads();

    // Hillis-Steele inclusive scan over per-thread sums
    for (int off = 1; off < SCAN_T; off <<= 1) {
        int v = (tid >= off) ? ssum[tid - off] : 0;
        __syncthreads();
        ssum[tid] += v;
        __syncthreads();
    }

    int run = (tid > 0) ? ssum[tid - 1] : 0;   // exclusive prefix of this chunk
    for (int i = start; i < end; i++) {
        g_rowptr[i] = run;
        g_pos[i]    = run;
        run += g_deg[i];
    }
    if (start <= n && end == n) g_rowptr[n] = run;
}

__global__ void k_norm(int n) {
    int i = blockIdx.x * blockDim.x + threadIdx.x;
    if (i < n) g_dinv[i] = rsqrtf((float)g_deg[i] + 1.0f);  // +1 self loop
}

// ---------------- CSR fill (int atomics only) -------------------------------
__global__ void k_csr_fill(const void* __restrict__ ei, int e) {
    int i = blockIdx.x * blockDim.x + threadIdx.x;
    if (i < e) {
        int s = edge_at(ei, i);
        int d = edge_at(ei, e + i);
        int slot = atomicAdd(&g_pos[d], 1);
        g_csr_src[slot] = s;
        g_csr_wt[slot]  = g_dinv[s] * g_dinv[d];
    }
}

// ---------------- h = X @ W  (packed f32x2 FMA inner loop) ------------------
// 64 threads / block, one row per thread, W in smem, X tile in padded smem.
__global__ void k_gemm(const float* __restrict__ X, int xstride,
                       const float* __restrict__ W, int n) {
    __shared__ __align__(16) float Ws[F * F];   // 16 KB
    __shared__ float xs[64 * 65];               // padded: no bank conflicts
    int tid  = threadIdx.x;
    int row0 = blockIdx.x * 64;

    for (int i = tid; i < F * F; i += 64) Ws[i] = W[i];
    for (int i = tid; i < 64 * F; i += 64) {
        int r = i >> 6, k = i & 63;
        int row = row0 + r;
        xs[r * 65 + k] = (row < n) ? X[(size_t)row * xstride + k] : 0.0f;
    }
    __syncthreads();

    int row = row0 + tid;
    if (row >= n) return;

    unsigned long long acc[F / 2];
#pragma unroll
    for (int j = 0; j < F / 2; j++) acc[j] = 0ULL;

    for (int k = 0; k < F; k++) {
        unsigned int xb = __float_as_uint(xs[tid * 65 + k]);
        unsigned long long xp;
        asm("mov.b64 %0, {%1, %1};" : "=l"(xp) : "r"(xb));
        const unsigned long long* wrow =
            (const unsigned long long*)&Ws[k * F];     // 256B-aligned rows
#pragma unroll
        for (int j = 0; j < F / 2; j++) {
            asm("fma.rn.f32x2 %0, %1, %2, %0;"
                : "+l"(acc[j]) : "l"(xp), "l"(wrow[j]));
        }
    }

    unsigned long long* hp = (unsigned long long*)(g_h + (size_t)row * F);
#pragma unroll
    for (int j = 0; j < F / 2; j++) hp[j] = acc[j];
}

// ---------------- pull-gather + self-loop + bias + relu + concat-store ------
// One warp per destination node. Lane handles feature lane & lane+32.
__global__ void k_gather(const float* __restrict__ bias,
                         float* __restrict__ out,
                         int coloff, int do_relu, int n) {
    int warp = (blockIdx.x * blockDim.x + threadIdx.x) >> 5;
    int lane = threadIdx.x & 31;
    if (warp >= n) return;

    int beg = g_rowptr[warp];
    int end = g_rowptr[warp + 1];
    float dv  = g_dinv[warp];
    float dv2 = dv * dv;

    const float* hn = g_h + (size_t)warp * F;
    float a0 = bias[lane]      + dv2 * hn[lane];
    float a1 = bias[lane + 32] + dv2 * hn[lane + 32];

    int j = beg;
    for (; j + 1 < end; j += 2) {
        int   s0 = g_csr_src[j],     s1 = g_csr_src[j + 1];
        float w0 = g_csr_wt[j],      w1 = g_csr_wt[j + 1];
        const float* h0 = g_h + (size_t)s0 * F;
        const float* h1 = g_h + (size_t)s1 * F;
        float v00 = h0[lane], v01 = h0[lane + 32];
        float v10 = h1[lane], v11 = h1[lane + 32];
        a0 += w0 * v00;  a1 += w0 * v01;
        a0 += w1 * v10;  a1 += w1 * v11;
    }
    if (j < end) {
        int   s = g_csr_src[j];
        float w = g_csr_wt[j];
        const float* hs = g_h + (size_t)s * F;
        a0 += w * hs[lane];
        a1 += w * hs[lane + 32];
    }

    if (do_relu) { a0 = fmaxf(a0, 0.0f); a1 = fmaxf(a1, 0.0f); }
    float* op = out + (size_t)warp * OUTC + coloff;
    op[lane]      = a0;
    op[lane + 32] = a1;
}

// ---------------- graph embedding: columnwise max over all nodes -----------
__global__ void k_gmax_partial(const float* __restrict__ emb, int n) {
    int c = threadIdx.x;                 // 0..191, coalesced across threads
    int b = blockIdx.x;
    int per = (n + GMAX_BLOCKS - 1) / GMAX_BLOCKS;
    int r0 = b * per;
    int r1 = min(n, r0 + per);
    float m = -3.4e38f;
    for (int r = r0; r < r1; r++)
        m = fmaxf(m, emb[(size_t)r * OUTC + c]);
    g_partial[b * OUTC + c] = m;
}

__global__ void k_gmax_final(float* __restrict__ out) {
    int c = threadIdx.x;
    float m = -3.4e38f;
    for (int b = 0; b < GMAX_BLOCKS; b++)
        m = fmaxf(m, g_partial[b * OUTC + c]);
    out[c] = m;
}

// ---------------- target-row logits (only row we need) ---------------------
__global__ void k_outrow(const float* __restrict__ emb,
                         const int* __restrict__ tptr,   // LE low word works
                         const float* __restrict__ fcW,  // for int32 and int64
                         const float* __restrict__ fcb,
                         float* __restrict__ out) {
    __shared__ float row[OUTC];
    int t = tptr[0];
    for (int i = threadIdx.x; i < OUTC; i += blockDim.x)
        row[i] = emb[(size_t)t * OUTC + i];
    __syncthreads();
    if (threadIdx.x < 4) {
        float s = fcb[threadIdx.x];
        for (int i = 0; i < OUTC; i++)
            s += row[i] * fcW[i * 4 + threadIdx.x];
        out[threadIdx.x] = s;
    }
}

// ---------------- launch ----------------------------------------------------
extern "C" void kernel_launch(void* const* d_in, const int* in_sizes, int n_in,
                              void* d_out, int out_size) {
    const float* x    = (const float*)d_in[0];
    const void*  ei   = d_in[1];                   // int32 or int64: detected
    /* d_in[2] = batch (all zeros, unused) */
    const int*   tptr = (const int*)d_in[3];       // target_node
    const float* W1   = (const float*)d_in[4];
    const float* b1   = (const float*)d_in[5];
    const float* W2   = (const float*)d_in[6];
    const float* b2   = (const float*)d_in[7];
    const float* W3   = (const float*)d_in[8];
    const float* b3   = (const float*)d_in[9];
    const float* fcW  = (const float*)d_in[10];
    const float* fcb  = (const float*)d_in[11];
    float* out = (float*)d_out;

    int n = in_sizes[0] / F;        // 50000
    int e = in_sizes[1] / 2;        // 800000 (element count same for i32/i64)

    int nb = (n + 255) / 256;
    int eb = (e + 255) / 256;
    int gb = (n + 63) / 64;
    int wb = (n * 32 + 255) / 256;  // warp-per-node gather

    // dtype probe + CSR + norm precompute (int atomics only)
    k_detect   <<<1, 32>>>(ei);
    k_deg_zero <<<nb, 256>>>(n);
    k_deg_count<<<eb, 256>>>(ei, e);
    k_scan     <<<1, SCAN_T>>>(n);
    k_norm     <<<nb, 256>>>(n);
    k_csr_fill <<<eb, 256>>>(ei, e);

    // layer 1: input x (stride 64) -> relu -> cols [0,64)
    k_gemm   <<<gb, 64>>>(x, F, W1, n);
    k_gather <<<wb, 256>>>(b1, out, 0, 1, n);

    // layer 2: input x1 = out+0 (stride 192) -> relu -> cols [64,128)
    k_gemm   <<<gb, 64>>>(out, OUTC, W2, n);
    k_gather <<<wb, 256>>>(b2, out, 64, 1, n);

    // layer 3: input x2 = out+64 (stride 192) -> no relu -> cols [128,192)
    k_gemm   <<<gb, 64>>>(out + 64, OUTC, W3, n);
    k_gather <<<wb, 256>>>(b3, out, 128, 0, n);

    // graph embedding (segment_max over the single graph)
    float* gemb = out + (size_t)n * OUTC;
    k_gmax_partial<<<GMAX_BLOCKS, OUTC>>>(out, n);
    k_gmax_final  <<<1, OUTC>>>(gemb);

    // target-node logits
    k_outrow<<<1, 192>>>(out, tptr, fcW, fcb, gemb + OUTC);
}

// round 7
// speedup vs baseline: 1.3435x; 1.3435x over previous
#include <cuda_runtime.h>

// Problem constants (fixed by the dataset)
#define NMAX   50000
#define EMAX   800000
#define F      64          // feature width of every layer
#define OUTC   192         // concat(x1,x2,x3) width
#define GMAX_BLOCKS 200
#define SCAN_B 512                       // elements (and threads) per scan block
#define SCAN_NB ((NMAX + SCAN_B - 1) / SCAN_B)   // 98

// ---------------- scratch (device globals: no allocation allowed) ----------
__device__ int   g_is64;                 // 1 if edge_index is int64, 0 if int32
__device__ int   g_deg[NMAX];
__device__ int   g_rowptr[NMAX + 1];
__device__ int   g_pos[NMAX];
__device__ float g_dinv[NMAX];
__device__ int   g_bsum[SCAN_NB];
__device__ int   g_boff[SCAN_NB];
__device__ int   g_csr_src[EMAX];
__device__ float g_csr_wt[EMAX];
__device__ __align__(16) float g_h[NMAX * F];   // h = X @ W of current layer
__device__ float g_partial[GMAX_BLOCKS * OUTC];

// ---------------- edge-index dtype detection --------------------------------
// Genuine int64 node ids are < NMAX. int32 data reinterpreted as int64 yields
// huge values (high word = a second node id, nonzero w.p. ~1 across 64 probes).
__global__ void k_detect(const void* __restrict__ ei) {
    if (threadIdx.x == 0) {
        const long long* p = (const long long*)ei;
        int is64 = 1;
        for (int i = 0; i < 64; i++) {
            long long v = p[i];
            if (v < 0 || v >= NMAX) { is64 = 0; break; }
        }
        g_is64 = is64;
    }
}

__device__ __forceinline__ int edge_at(const void* ei, int idx) {
    if (g_is64) return (int)((const long long*)ei)[idx];
    return ((const int*)ei)[idx];
}

// ---------------- degree histogram ------------------------------------------
__global__ void k_deg_zero(int n) {
    int i = blockIdx.x * blockDim.x + threadIdx.x;
    if (i < n) g_deg[i] = 0;
}

__global__ void k_deg_count(const void* __restrict__ ei, int e) {
    int i = blockIdx.x * blockDim.x + threadIdx.x;
    if (i < e) atomicAdd(&g_deg[edge_at(ei, e + i)], 1);   // row 1 = dst
}

// ---------------- hierarchical exclusive scan over degrees ------------------
// Pass 1: per-block (512 elems) sum
__global__ void k_scan1(int n) {
    __shared__ int sh[SCAN_B];
    int i = blockIdx.x * SCAN_B + threadIdx.x;
    sh[threadIdx.x] = (i < n) ? g_deg[i] : 0;
    __syncthreads();
    for (int off = SCAN_B / 2; off > 0; off >>= 1) {
        if (threadIdx.x < off) sh[threadIdx.x] += sh[threadIdx.x + off];
        __syncthreads();
    }
    if (threadIdx.x == 0) g_bsum[blockIdx.x] = sh[0];
}

// Pass 2: one block scans the SCAN_NB block sums (exclusive), writes total
__global__ void k_scan2(int n) {
    __shared__ int sh[128];
    int tid = threadIdx.x;                      // 128 threads, SCAN_NB <= 128
    int v = (tid < SCAN_NB) ? g_bsum[tid] : 0;
    sh[tid] = v;
    __syncthreads();
    for (int off = 1; off < 128; off <<= 1) {
        int u = (tid >= off) ? sh[tid - off] : 0;
        __syncthreads();
        sh[tid] += u;
        __syncthreads();
    }
    if (tid < SCAN_NB) g_boff[tid] = sh[tid] - v;   // exclusive
    if (tid == 127) g_rowptr[n] = sh[127];          // total edge count
}

// Pass 3: per-block exclusive scan + offset -> rowptr & pos
__global__ void k_scan3(int n) {
    __shared__ int sh[SCAN_B];
    int tid = threadIdx.x;
    int i = blockIdx.x * SCAN_B + tid;
    int v = (i < n) ? g_deg[i] : 0;
    sh[tid] = v;
    __syncthreads();
    for (int off = 1; off < SCAN_B; off <<= 1) {
        int u = (tid >= off) ? sh[tid - off] : 0;
        __syncthreads();
        sh[tid] += u;
        __syncthreads();
    }
    if (i < n) {
        int r = g_boff[blockIdx.x] + sh[tid] - v;   // exclusive prefix
        g_rowptr[i] = r;
        g_pos[i]    = r;
    }
}

__global__ void k_norm(int n) {
    int i = blockIdx.x * blockDim.x + threadIdx.x;
    if (i < n) g_dinv[i] = rsqrtf((float)g_deg[i] + 1.0f);  // +1 self loop
}

// ---------------- CSR fill (int atomics only) -------------------------------
__global__ void k_csr_fill(const void* __restrict__ ei, int e) {
    int i = blockIdx.x * blockDim.x + threadIdx.x;
    if (i < e) {
        int s = edge_at(ei, i);
        int d = edge_at(ei, e + i);
        int slot = atomicAdd(&g_pos[d], 1);
        g_csr_src[slot] = s;
        g_csr_wt[slot]  = g_dinv[s] * g_dinv[d];
    }
}

// ---------------- h = X @ W  (packed f32x2 FMA inner loop) ------------------
// 64 threads / block, one row per thread, W in smem, X tile in padded smem.
__global__ void k_gemm(const float* __restrict__ X, int xstride,
                       const float* __restrict__ W, int n) {
    __shared__ __align__(16) float Ws[F * F];   // 16 KB
    __shared__ float xs[64 * 65];               // padded: no bank conflicts
    int tid  = threadIdx.x;
    int row0 = blockIdx.x * 64;

    for (int i = tid; i < F * F; i += 64) Ws[i] = W[i];
    for (int i = tid; i < 64 * F; i += 64) {
        int r = i >> 6, k = i & 63;
        int row = row0 + r;
        xs[r * 65 + k] = (row < n) ? X[(size_t)row * xstride + k] : 0.0f;
    }
    __syncthreads();

    int row = row0 + tid;
    if (row >= n) return;

    unsigned long long acc[F / 2];
#pragma unroll
    for (int j = 0; j < F / 2; j++) acc[j] = 0ULL;

    for (int k = 0; k < F; k++) {
        unsigned int xb = __float_as_uint(xs[tid * 65 + k]);
        unsigned long long xp;
        asm("mov.b64 %0, {%1, %1};" : "=l"(xp) : "r"(xb));
        const unsigned long long* wrow =
            (const unsigned long long*)&Ws[k * F];     // 256B-aligned rows
#pragma unroll
        for (int j = 0; j < F / 2; j++) {
            asm("fma.rn.f32x2 %0, %1, %2, %0;"
                : "+l"(acc[j]) : "l"(xp), "l"(wrow[j]));
        }
    }

    unsigned long long* hp = (unsigned long long*)(g_h + (size_t)row * F);
#pragma unroll
    for (int j = 0; j < F / 2; j++) hp[j] = acc[j];
}

// ---------------- pull-gather + self-loop + bias + relu + concat-store ------
// One warp per destination node. Lane handles feature lane & lane+32.
// Edge loop unrolled 4x with front-batched loads for MLP.
__global__ void k_gather(const float* __restrict__ bias,
                         float* __restrict__ out,
                         int coloff, int do_relu, int n) {
    int warp = (blockIdx.x * blockDim.x + threadIdx.x) >> 5;
    int lane = threadIdx.x & 31;
    if (warp >= n) return;

    int beg = g_rowptr[warp];
    int end = g_rowptr[warp + 1];
    float dv  = g_dinv[warp];
    float dv2 = dv * dv;

    const float* hn = g_h + (size_t)warp * F;
    float a0 = bias[lane]      + dv2 * hn[lane];
    float a1 = bias[lane + 32] + dv2 * hn[lane + 32];

    int j = beg;
    for (; j + 3 < end; j += 4) {
        int   s0 = g_csr_src[j],   s1 = g_csr_src[j+1];
        int   s2 = g_csr_src[j+2], s3 = g_csr_src[j+3];
        float w0 = g_csr_wt[j],    w1 = g_csr_wt[j+1];
        float w2 = g_csr_wt[j+2],  w3 = g_csr_wt[j+3];
        const float* h0 = g_h + (size_t)s0 * F;
        const float* h1 = g_h + (size_t)s1 * F;
        const float* h2 = g_h + (size_t)s2 * F;
        const float* h3 = g_h + (size_t)s3 * F;
        // front-batch all 8 loads (MLP=8), then FMA
        float v00 = h0[lane], v01 = h0[lane + 32];
        float v10 = h1[lane], v11 = h1[lane + 32];
        float v20 = h2[lane], v21 = h2[lane + 32];
        float v30 = h3[lane], v31 = h3[lane + 32];
        a0 += w0 * v00;  a1 += w0 * v01;
        a0 += w1 * v10;  a1 += w1 * v11;
        a0 += w2 * v20;  a1 += w2 * v21;
        a0 += w3 * v30;  a1 += w3 * v31;
    }
    for (; j < end; j++) {
        int   s = g_csr_src[j];
        float w = g_csr_wt[j];
        const float* hs = g_h + (size_t)s * F;
        a0 += w * hs[lane];
        a1 += w * hs[lane + 32];
    }

    if (do_relu) { a0 = fmaxf(a0, 0.0f); a1 = fmaxf(a1, 0.0f); }
    float* op = out + (size_t)warp * OUTC + coloff;
    op[lane]      = a0;
    op[lane + 32] = a1;
}

// ---------------- graph embedding: columnwise max over all nodes -----------
__global__ void k_gmax_partial(const float* __restrict__ emb, int n) {
    int c = threadIdx.x;                 // 0..191, coalesced across threads
    int b = blockIdx.x;
    int per = (n + GMAX_BLOCKS - 1) / GMAX_BLOCKS;
    int r0 = b * per;
    int r1 = min(n, r0 + per);
    float m = -3.4e38f;
    for (int r = r0; r < r1; r++)
        m = fmaxf(m, emb[(size_t)r * OUTC + c]);
    g_partial[b * OUTC + c] = m;
}

__global__ void k_gmax_final(float* __restrict__ out) {
    int c = threadIdx.x;
    float m = -3.4e38f;
    for (int b = 0; b < GMAX_BLOCKS; b++)
        m = fmaxf(m, g_partial[b * OUTC + c]);
    out[c] = m;
}

// ---------------- target-row logits (only row we need) ---------------------
__global__ void k_outrow(const float* __restrict__ emb,
                         const int* __restrict__ tptr,   // LE low word works
                         const float* __restrict__ fcW,  // for int32 and int64
                         const float* __restrict__ fcb,
                         float* __restrict__ out) {
    __shared__ float row[OUTC];
    int t = tptr[0];
    for (int i = threadIdx.x; i < OUTC; i += blockDim.x)
        row[i] = emb[(size_t)t * OUTC + i];
    __syncthreads();
    if (threadIdx.x < 4) {
        float s = fcb[threadIdx.x];
        for (int i = 0; i < OUTC; i++)
            s += row[i] * fcW[i * 4 + threadIdx.x];
        out[threadIdx.x] = s;
    }
}

// ---------------- launch ----------------------------------------------------
extern "C" void kernel_launch(void* const* d_in, const int* in_sizes, int n_in,
                              void* d_out, int out_size) {
    const float* x    = (const float*)d_in[0];
    const void*  ei   = d_in[1];                   // int32 or int64: detected
    /* d_in[2] = batch (all zeros, unused) */
    const int*   tptr = (const int*)d_in[3];       // target_node
    const float* W1   = (const float*)d_in[4];
    const float* b1   = (const float*)d_in[5];
    const float* W2   = (const float*)d_in[6];
    const float* b2   = (const float*)d_in[7];
    const float* W3   = (const float*)d_in[8];
    const float* b3   = (const float*)d_in[9];
    const float* fcW  = (const float*)d_in[10];
    const float* fcb  = (const float*)d_in[11];
    float* out = (float*)d_out;

    int n = in_sizes[0] / F;        // 50000
    int e = in_sizes[1] / 2;        // 800000 (element count same for i32/i64)

    int nb = (n + 255) / 256;
    int eb = (e + 255) / 256;
    int gb = (n + 63) / 64;
    int wb = (n * 32 + 255) / 256;  // warp-per-node gather
    int sb = (n + SCAN_B - 1) / SCAN_B;

    // dtype probe + CSR + norm precompute (int atomics only)
    k_detect   <<<1, 32>>>(ei);
    k_deg_zero <<<nb, 256>>>(n);
    k_deg_count<<<eb, 256>>>(ei, e);
    k_norm     <<<nb, 256>>>(n);
    k_scan1    <<<sb, SCAN_B>>>(n);
    k_scan2    <<<1, 128>>>(n);
    k_scan3    <<<sb, SCAN_B>>>(n);
    k_csr_fill <<<eb, 256>>>(ei, e);

    // layer 1: input x (stride 64) -> relu -> cols [0,64)
    k_gemm   <<<gb, 64>>>(x, F, W1, n);
    k_gather <<<wb, 256>>>(b1, out, 0, 1, n);

    // layer 2: input x1 = out+0 (stride 192) -> relu -> cols [64,128)
    k_gemm   <<<gb, 64>>>(out, OUTC, W2, n);
    k_gather <<<wb, 256>>>(b2, out, 64, 1, n);

    // layer 3: input x2 = out+64 (stride 192) -> no relu -> cols [128,192)
    k_gemm   <<<gb, 64>>>(out + 64, OUTC, W3, n);
    k_gather <<<wb, 256>>>(b3, out, 128, 0, n);

    // graph embedding (segment_max over the single graph)
    float* gemb = out + (size_t)n * OUTC;
    k_gmax_partial<<<GMAX_BLOCKS, OUTC>>>(out, n);
    k_gmax_final  <<<1, OUTC>>>(gemb);

    // target-node logits
    k_outrow<<<1, 192>>>(out, tptr, fcW, fcb, gemb + OUTC);
}

// round 9
// speedup vs baseline: 1.4126x; 1.0514x over previous
#include <cuda_runtime.h>

// Problem constants (fixed by the dataset)
#define NMAX   50000
#define EMAX   800000
#define F      64          // feature width of every layer
#define OUTC   192         // concat(x1,x2,x3) width
#define GMAX_BLOCKS 200
#define SCAN_B 512
#define SCAN_NB ((NMAX + SCAN_B - 1) / SCAN_B)   // 98

// ---------------- scratch (device globals: no allocation allowed) ----------
__device__ int   g_is64;                 // 1 if edge_index is int64
__device__ int   g_deg[NMAX];
__device__ int   g_rowptr[NMAX + 1];
__device__ int   g_pos[NMAX];
__device__ float g_dinv[NMAX];
__device__ int   g_bsum[SCAN_NB];
__device__ int   g_boff[SCAN_NB];
__device__ int2  g_csr[EMAX];            // packed {src, wt_bits} per edge
__device__ __align__(16) float g_h[NMAX * F];   // h = X @ W of current layer
__device__ float g_partial[GMAX_BLOCKS * OUTC];

// ---------------- init: zero degrees + parallel dtype probe -----------------
// Genuine int64 node ids are < NMAX; int32 data reinterpreted as int64 yields
// huge/negative values with overwhelming probability across 64 probes.
__global__ void k_init(const void* __restrict__ ei, int n) {
    int i = blockIdx.x * blockDim.x + threadIdx.x;
    if (i < n) g_deg[i] = 0;
    if (blockIdx.x == 0 && threadIdx.x < 32) {
        const long long* p = (const long long*)ei;
        long long v0 = p[threadIdx.x * 2];
        long long v1 = p[threadIdx.x * 2 + 1];
        int bad = (v0 < 0 || v0 >= NMAX || v1 < 0 || v1 >= NMAX);
        unsigned m = __ballot_sync(0xFFFFFFFFu, bad);
        if (threadIdx.x == 0) g_is64 = (m == 0) ? 1 : 0;
    }
}

__device__ __forceinline__ int edge_at(const void* ei, int idx) {
    if (g_is64) return (int)((const long long*)ei)[idx];
    return ((const int*)ei)[idx];
}

// ---------------- degree histogram ------------------------------------------
__global__ void k_deg_count(const void* __restrict__ ei, int e) {
    int i = blockIdx.x * blockDim.x + threadIdx.x;
    if (i < e) atomicAdd(&g_deg[edge_at(ei, e + i)], 1);   // row 1 = dst
}

// ---------------- hierarchical exclusive scan over degrees ------------------
__global__ void k_scan1(int n) {
    __shared__ int sh[SCAN_B];
    int i = blockIdx.x * SCAN_B + threadIdx.x;
    sh[threadIdx.x] = (i < n) ? g_deg[i] : 0;
    __syncthreads();
    for (int off = SCAN_B / 2; off > 0; off >>= 1) {
        if (threadIdx.x < off) sh[threadIdx.x] += sh[threadIdx.x + off];
        __syncthreads();
    }
    if (threadIdx.x == 0) g_bsum[blockIdx.x] = sh[0];
}

__global__ void k_scan2(int n) {
    __shared__ int sh[128];
    int tid = threadIdx.x;                       // 128 threads, SCAN_NB <= 128
    int v = (tid < SCAN_NB) ? g_bsum[tid] : 0;
    sh[tid] = v;
    __syncthreads();
    for (int off = 1; off < 128; off <<= 1) {
        int u = (tid >= off) ? sh[tid - off] : 0;
        __syncthreads();
        sh[tid] += u;
        __syncthreads();
    }
    if (tid < SCAN_NB) g_boff[tid] = sh[tid] - v;    // exclusive
    if (tid == 127) g_rowptr[n] = sh[127];
}

// Pass 3: per-block exclusive scan + offset -> rowptr & pos; fused dinv.
__global__ void k_scan3(int n) {
    __shared__ int sh[SCAN_B];
    int tid = threadIdx.x;
    int i = blockIdx.x * SCAN_B + tid;
    int v = (i < n) ? g_deg[i] : 0;
    sh[tid] = v;
    __syncthreads();
    for (int off = 1; off < SCAN_B; off <<= 1) {
        int u = (tid >= off) ? sh[tid - off] : 0;
        __syncthreads();
        sh[tid] += u;
        __syncthreads();
    }
    if (i < n) {
        int r = g_boff[blockIdx.x] + sh[tid] - v;    // exclusive prefix
        g_rowptr[i] = r;
        g_pos[i]    = r;
        g_dinv[i]   = rsqrtf((float)v + 1.0f);       // +1 self loop
    }
}

// ---------------- CSR fill (packed int2, int atomics only) ------------------
__global__ void k_csr_fill(const void* __restrict__ ei, int e) {
    int i = blockIdx.x * blockDim.x + threadIdx.x;
    if (i < e) {
        int s = edge_at(ei, i);
        int d = edge_at(ei, e + i);
        int slot = atomicAdd(&g_pos[d], 1);
        float wt = g_dinv[s] * g_dinv[d];
        g_csr[slot] = make_int2(s, __float_as_int(wt));
    }
}

// ---------------- h = X @ W  (packed f32x2 FMA inner loop) ------------------
__global__ void k_gemm(const float* __restrict__ X, int xstride,
                       const float* __restrict__ W, int n) {
    __shared__ __align__(16) float Ws[F * F];   // 16 KB
    __shared__ float xs[64 * 65];               // padded: no bank conflicts
    int tid  = threadIdx.x;
    int row0 = blockIdx.x * 64;

    for (int i = tid; i < F * F; i += 64) Ws[i] = W[i];
    for (int i = tid; i < 64 * F; i += 64) {
        int r = i >> 6, k = i & 63;
        int row = row0 + r;
        xs[r * 65 + k] = (row < n) ? X[(size_t)row * xstride + k] : 0.0f;
    }
    __syncthreads();

    int row = row0 + tid;
    if (row >= n) return;

    unsigned long long acc[F / 2];
#pragma unroll
    for (int j = 0; j < F / 2; j++) acc[j] = 0ULL;

    for (int k = 0; k < F; k++) {
        unsigned int xb = __float_as_uint(xs[tid * 65 + k]);
        unsigned long long xp;
        asm("mov.b64 %0, {%1, %1};" : "=l"(xp) : "r"(xb));
        const unsigned long long* wrow =
            (const unsigned long long*)&Ws[k * F];
#pragma unroll
        for (int j = 0; j < F / 2; j++) {
            asm("fma.rn.f32x2 %0, %1, %2, %0;"
                : "+l"(acc[j]) : "l"(xp), "l"(wrow[j]));
        }
    }

    unsigned long long* hp = (unsigned long long*)(g_h + (size_t)row * F);
#pragma unroll
    for (int j = 0; j < F / 2; j++) hp[j] = acc[j];
}

// ---------------- pull-gather + self-loop + bias + relu + concat-store ------
// One warp per destination node; lane = feature lane & lane+32.
// Edge loop unrolled 8x, packed int2 meta, all loads front-batched (MLP=16+8).
__global__ void k_gather(const float* __restrict__ bias,
                         float* __restrict__ out,
                         int coloff, int do_relu, int n) {
    int warp = (blockIdx.x * blockDim.x + threadIdx.x) >> 5;
    int lane = threadIdx.x & 31;
    if (warp >= n) return;

    int beg = g_rowptr[warp];
    int end = g_rowptr[warp + 1];
    float dv  = g_dinv[warp];
    float dv2 = dv * dv;

    const float* __restrict__ hb = g_h + lane;      // lane-offset base
    const float* hn = hb + (size_t)warp * F;
    float a0 = bias[lane]      + dv2 * hn[0];
    float a1 = bias[lane + 32] + dv2 * hn[32];

    int j = beg;
#define EDGE_LOAD(k)                                     \
    int2 m##k = g_csr[j + k];                            \
    const float* p##k = hb + (size_t)m##k.x * F;         \
    float w##k = __int_as_float(m##k.y);

    for (; j + 7 < end; j += 8) {
        EDGE_LOAD(0) EDGE_LOAD(1) EDGE_LOAD(2) EDGE_LOAD(3)
        EDGE_LOAD(4) EDGE_LOAD(5) EDGE_LOAD(6) EDGE_LOAD(7)
        float v00 = p0[0], v01 = p0[32];
        float v10 = p1[0], v11 = p1[32];
        float v20 = p2[0], v21 = p2[32];
        float v30 = p3[0], v31 = p3[32];
        float v40 = p4[0], v41 = p4[32];
        float v50 = p5[0], v51 = p5[32];
        float v60 = p6[0], v61 = p6[32];
        float v70 = p7[0], v71 = p7[32];
        a0 += w0 * v00;  a1 += w0 * v01;
        a0 += w1 * v10;  a1 += w1 * v11;
        a0 += w2 * v20;  a1 += w2 * v21;
        a0 += w3 * v30;  a1 += w3 * v31;
        a0 += w4 * v40;  a1 += w4 * v41;
        a0 += w5 * v50;  a1 += w5 * v51;
        a0 += w6 * v60;  a1 += w6 * v61;
        a0 += w7 * v70;  a1 += w7 * v71;
    }
    for (; j + 1 < end; j += 2) {
        EDGE_LOAD(0) EDGE_LOAD(1)
        float v00 = p0[0], v01 = p0[32];
        float v10 = p1[0], v11 = p1[32];
        a0 += w0 * v00;  a1 += w0 * v01;
        a0 += w1 * v10;  a1 += w1 * v11;
    }
    if (j < end) {
        EDGE_LOAD(0)
        a0 += w0 * p0[0];
        a1 += w0 * p0[32];
    }
#undef EDGE_LOAD

    if (do_relu) { a0 = fmaxf(a0, 0.0f); a1 = fmaxf(a1, 0.0f); }
    float* op = out + (size_t)warp * OUTC + coloff;
    op[lane]      = a0;
    op[lane + 32] = a1;
}

// ---------------- graph embedding: columnwise max over all nodes -----------
__global__ void k_gmax_partial(const float* __restrict__ emb, int n) {
    int c = threadIdx.x;                 // 0..191, coalesced across threads
    int b = blockIdx.x;
    int per = (n + GMAX_BLOCKS - 1) / GMAX_BLOCKS;
    int r0 = b * per;
    int r1 = min(n, r0 + per);
    float m = -3.4e38f;
    for (int r = r0; r < r1; r++)
        m = fmaxf(m, emb[(size_t)r * OUTC + c]);
    g_partial[b * OUTC + c] = m;
}

__global__ void k_gmax_final(float* __restrict__ out) {
    int c = threadIdx.x;
    float m = -3.4e38f;
    for (int b = 0; b < GMAX_BLOCKS; b++)
        m = fmaxf(m, g_partial[b * OUTC + c]);
    out[c] = m;
}

// ---------------- target-row logits (only row we need) ---------------------
__global__ void k_outrow(const float* __restrict__ emb,
                         const int* __restrict__ tptr,   // LE low word works
                         const float* __restrict__ fcW,  // for int32 and int64
                         const float* __restrict__ fcb,
                         float* __restrict__ out) {
    __shared__ float row[OUTC];
    int t = tptr[0];
    for (int i = threadIdx.x; i < OUTC; i += blockDim.x)
        row[i] = emb[(size_t)t * OUTC + i];
    __syncthreads();
    if (threadIdx.x < 4) {
        float s = fcb[threadIdx.x];
        for (int i = 0; i < OUTC; i++)
            s += row[i] * fcW[i * 4 + threadIdx.x];
        out[threadIdx.x] = s;
    }
}

// ---------------- launch ----------------------------------------------------
extern "C" void kernel_launch(void* const* d_in, const int* in_sizes, int n_in,
                              void* d_out, int out_size) {
    const float* x    = (const float*)d_in[0];
    const void*  ei   = d_in[1];                   // int32 or int64: detected
    /* d_in[2] = batch (all zeros, unused) */
    const int*   tptr = (const int*)d_in[3];       // target_node
    const float* W1   = (const float*)d_in[4];
    const float* b1   = (const float*)d_in[5];
    const float* W2   = (const float*)d_in[6];
    const float* b2   = (const float*)d_in[7];
    const float* W3   = (const float*)d_in[8];
    const float* b3   = (const float*)d_in[9];
    const float* fcW  = (const float*)d_in[10];
    const float* fcb  = (const float*)d_in[11];
    float* out = (float*)d_out;

    int n = in_sizes[0] / F;        // 50000
    int e = in_sizes[1] / 2;        // 800000

    int nb = (n + 255) / 256;
    int eb = (e + 255) / 256;
    int gb = (n + 63) / 64;
    int wb = (n * 32 + 255) / 256;  // warp-per-node gather
    int sb = (n + SCAN_B - 1) / SCAN_B;

    // prologue: dtype probe + degree histogram + scan + CSR fill
    k_init     <<<nb, 256>>>(ei, n);
    k_deg_count<<<eb, 256>>>(ei, e);
    k_scan1    <<<sb, SCAN_B>>>(n);
    k_scan2    <<<1, 128>>>(n);
    k_scan3    <<<sb, SCAN_B>>>(n);   // rowptr + pos + dinv
    k_csr_fill <<<eb, 256>>>(ei, e);

    // layer 1: input x (stride 64) -> relu -> cols [0,64)
    k_gemm   <<<gb, 64>>>(x, F, W1, n);
    k_gather <<<wb, 256>>>(b1, out, 0, 1, n);

    // layer 2: input x1 = out+0 (stride 192) -> relu -> cols [64,128)
    k_gemm   <<<gb, 64>>>(out, OUTC, W2, n);
    k_gather <<<wb, 256>>>(b2, out, 64, 1, n);

    // layer 3: input x2 = out+64 (stride 192) -> no relu -> cols [128,192)
    k_gemm   <<<gb, 64>>>(out + 64, OUTC, W3, n);
    k_gather <<<wb, 256>>>(b3, out, 128, 0, n);

    // graph embedding (segment_max over the single graph)
    float* gemb = out + (size_t)n * OUTC;
    k_gmax_partial<<<GMAX_BLOCKS, OUTC>>>(out, n);
    k_gmax_final  <<<1, OUTC>>>(gemb);

    // target-node logits
    k_outrow<<<1, 192>>>(out, tptr, fcW, fcb, gemb + OUTC);
}